// round 13
// baseline (speedup 1.0000x reference)
#include <cuda_runtime.h>
#include <cstdint>

// Fixed problem dims
#define BB 2
#define DD 160
#define HH 192
#define WW 160
#define CZ 40                 // z-chunk depth per block
#define NQ 40                 // WW/4 quads per row
#define BX (NQ * 2)           // 80: quad id = tx>>1, tensor select = tx&1
#define BY 4                  // rows per block
#define NTHREADS (BX * BY)    // 320
#define GY (HH / BY)          // 48
#define NCID (BB * DD / CZ)   // 8 z-chunks
#define NBLK (GY * NCID)      // 384
#define PLANE (HH * WW)
#define NVOX ((double)BB * DD * HH * WW)
#define FULL 0xffffffffu

// smem staging ring
#define RSTR 168              // floats per row slot (672B: 16B-multiple, bank-skewed)
#define TSTR (6 * RSTR)       // tensor stride within a buffer (1008 floats)
#define BSTR (2 * TSTR)       // plane-buffer stride (2016 floats)
#define NBUF 4                // ring depth
#define NCOPY 480             // 12 rows * 40 x-chunks of 16B
#define NP (CZ + 2)           // planes touched per chunk

typedef unsigned long long u64;

__device__ float g_partial[NBLK];
__device__ unsigned int g_done = 0;

// ---------- packed f32x2 helpers (sm_100+) ----------
__device__ __forceinline__ u64 pack2(float lo, float hi) {
    u64 r; asm("mov.b64 %0, {%1,%2};" : "=l"(r) : "f"(lo), "f"(hi)); return r;
}
__device__ __forceinline__ void unpack2(u64 v, float& lo, float& hi) {
    asm("mov.b64 {%0,%1}, %2;" : "=f"(lo), "=f"(hi) : "l"(v));
}
__device__ __forceinline__ u64 fma2(u64 a, u64 b, u64 c) {
    u64 d; asm("fma.rn.f32x2 %0, %1, %2, %3;" : "=l"(d) : "l"(a), "l"(b), "l"(c)); return d;
}
__device__ __forceinline__ u64 add2(u64 a, u64 b) {
    u64 d; asm("add.rn.f32x2 %0, %1, %2;" : "=l"(d) : "l"(a), "l"(b)); return d;
}
__device__ __forceinline__ u64 sub2(u64 a, u64 b) {
    u64 d; asm("sub.rn.f32x2 %0, %1, %2;" : "=l"(d) : "l"(a), "l"(b)); return d;
}
__device__ __forceinline__ float fsqrt_approx(float x) {
    float r; asm("sqrt.approx.f32 %0, %1;" : "=f"(r) : "f"(x)); return r;
}

// cp.async 16B with zero-fill (src_size = 0 when invalid)
__device__ __forceinline__ void cp16(float* dst, const float* src, bool valid) {
    unsigned int d = (unsigned int)__cvta_generic_to_shared(dst);
    int sz = valid ? 16 : 0;
    asm volatile("cp.async.cg.shared.global [%0], [%1], 16, %2;"
                 :: "r"(d), "l"(src), "r"(sz));
}
#define CP_COMMIT() asm volatile("cp.async.commit_group;")
#define CP_WAIT2()  asm volatile("cp.async.wait_group 2;")

struct ABCp { u64 aA, aB, bA, bB, cA, cB; };   // a=sx*sy, b=dx*sy, c=sx*dy

// Stage one plane's 12 rows (2 tensors x 6 y-rows) into ring buffer bufI.
__device__ __forceinline__ void load_plane(float* __restrict__ sbuf, int bufI,
                                           const float* __restrict__ pred,
                                           const float* __restrict__ targ,
                                           size_t batchOff, int z, int ybase, int tid) {
    const bool zv = (z >= 0) && (z < DD);
    float* bb = sbuf + bufI * BSTR;
    #pragma unroll
    for (int pass = 0; pass < 2; ++pass) {
        const int idx = tid + pass * NTHREADS;
        if (idx < NCOPY) {
            const int r = idx / 40;          // 0..11
            const int c = idx % 40;          // 16B chunk within row
            const int tn = r / 6;            // 0 = pred, 1 = targ
            const int rr = r % 6;
            const int yrow = ybase - 1 + rr;
            const bool valid = zv && (yrow >= 0) && (yrow < HH);
            const float* base = tn ? targ : pred;
            const float* gsrc = valid
                ? base + batchOff + ((size_t)z * HH + yrow) * WW + c * 4
                : base;                       // clamped; not read (src_size=0)
            float* dst = bb + tn * TSTR + rr * RSTR + c * 4;
            cp16(dst, gsrc, valid);
        }
    }
}

// Compute packed per-lane partials for one plane from the smem ring.
// tbase = sbuf + buf*BSTR + sel*TSTR ; rows ty, ty+1, ty+2 are y-1, y, y+1.
__device__ __forceinline__ ABCp plane_abc(const float* __restrict__ tbase,
                                          int ty, int x0, bool hasM, bool hasP,
                                          u64 TWO2) {
    const float* r0 = tbase + ty * RSTR;
    const float* r1 = r0 + RSTR;
    const float* r2 = r1 + RSTR;

    ulonglong2 q0 = *reinterpret_cast<const ulonglong2*>(r0 + x0);
    ulonglong2 q1 = *reinterpret_cast<const ulonglong2*>(r1 + x0);
    ulonglong2 q2 = *reinterpret_cast<const ulonglong2*>(r2 + x0);

    float em0 = hasM ? r0[x0 - 1] : 0.f;
    float em1 = hasM ? r1[x0 - 1] : 0.f;
    float em2 = hasM ? r2[x0 - 1] : 0.f;
    float ep0 = hasP ? r0[x0 + 4] : 0.f;
    float ep1 = hasP ? r1[x0 + 4] : 0.f;
    float ep2 = hasP ? r2[x0 + 4] : 0.f;

    // y-stage
    u64 sA = add2(fma2(TWO2, q1.x, q0.x), q2.x);
    u64 sB = add2(fma2(TWO2, q1.y, q0.y), q2.y);
    u64 dA = sub2(q2.x, q0.x);
    u64 dB = sub2(q2.y, q0.y);
    float sm = fmaf(2.f, em1, em0) + em2;
    float dm = em2 - em0;
    float sp = fmaf(2.f, ep1, ep0) + ep2;
    float dp = ep2 - ep0;

    float s0, s1, s2, s3, d0, d1, d2, d3;
    unpack2(sA, s0, s1); unpack2(sB, s2, s3);
    unpack2(dA, d0, d1); unpack2(dB, d2, d3);

    // x-stage on shifted packets
    u64 sL = pack2(sm, s0), sM = pack2(s1, s2), sR = pack2(s3, sp);
    u64 dL = pack2(dm, d0), dM = pack2(d1, d2), dR = pack2(d3, dp);
    ABCp o;
    o.aA = add2(fma2(TWO2, sA, sL), sM);
    o.aB = add2(fma2(TWO2, sB, sM), sR);
    o.bA = sub2(sM, sL);
    o.bB = sub2(sR, sM);
    o.cA = add2(fma2(TWO2, dA, dL), dM);
    o.cB = add2(fma2(TWO2, dB, dM), dR);
    return o;
}

// z-combine + magnitude, exchange with partner lane; BOTH lanes accumulate
// (total is 2x the true sum; final scale = 0.5/NVOX).
__device__ __forceinline__ float emit4(const ABCp& m2, const ABCp& m1, const ABCp& c,
                                       u64 TWO2, u64 EPS2) {
    u64 gxA = add2(fma2(TWO2, m1.bA, m2.bA), c.bA);
    u64 gxB = add2(fma2(TWO2, m1.bB, m2.bB), c.bB);
    u64 gyA = add2(fma2(TWO2, m1.cA, m2.cA), c.cA);
    u64 gyB = add2(fma2(TWO2, m1.cB, m2.cB), c.cB);
    u64 gzA = sub2(c.aA, m2.aA);
    u64 gzB = sub2(c.aB, m2.aB);
    u64 ssA = fma2(gxA, gxA, fma2(gyA, gyA, fma2(gzA, gzA, EPS2)));
    u64 ssB = fma2(gxB, gxB, fma2(gyB, gyB, fma2(gzB, gzB, EPS2)));
    float u0, u1, u2, u3;
    unpack2(ssA, u0, u1); unpack2(ssB, u2, u3);
    float g0 = fsqrt_approx(u0);
    float g1 = fsqrt_approx(u1);
    float g2 = fsqrt_approx(u2);
    float g3 = fsqrt_approx(u3);
    float o0 = __shfl_xor_sync(FULL, g0, 1);
    float o1 = __shfl_xor_sync(FULL, g1, 1);
    float o2 = __shfl_xor_sync(FULL, g2, 1);
    float o3 = __shfl_xor_sync(FULL, g3, 1);
    return fabsf(g0 - o0) + fabsf(g1 - o1) + fabsf(g2 - o2) + fabsf(g3 - o3);
}

__global__ __launch_bounds__(NTHREADS, 3)
void sobel_loss_fused(const float* __restrict__ pred, const float* __restrict__ targ,
                      float* __restrict__ out) {
    __shared__ float sbuf[NBUF * BSTR];        // 32256 B ring
    __shared__ float wsum[NTHREADS / 32];
    __shared__ int lastFlag;

    const int tx   = threadIdx.x;
    const int ty   = threadIdx.y;
    const int quad = tx >> 1;
    const int sel  = tx & 1;                  // 0 = pred, 1 = target
    const int x0   = quad * 4;
    const bool hasM = (quad > 0);
    const bool hasP = (quad < NQ - 1);
    const int tid  = ty * BX + tx;
    const int wid  = tid >> 5;
    const int lane = tid & 31;

    const u64 TWO2 = pack2(2.f, 2.f);
    const u64 EPS2 = pack2(1e-8f, 1e-8f);

    const int cid    = blockIdx.z;             // 0..7
    const int b      = cid >> 2;
    const int zstart = (cid & 3) * CZ;
    const int ybase  = blockIdx.y * BY;
    const size_t batchOff = (size_t)b * DD * PLANE;

    const float* tbase0 = sbuf + sel * TSTR;   // tensor base inside buffer 0

    // ---------- pipeline prologue: stage planes 0,1,2 ----------
    load_plane(sbuf, 0, pred, targ, batchOff, zstart - 1, ybase, tid); CP_COMMIT();
    load_plane(sbuf, 1, pred, targ, batchOff, zstart,     ybase, tid); CP_COMMIT();
    load_plane(sbuf, 2, pred, targ, batchOff, zstart + 1, ybase, tid); CP_COMMIT();

    float acc = 0.f;
    ABCp m2, m1;

    #pragma unroll 1
    for (int j = 0; j < NP; ++j) {
        CP_WAIT2();            // groups <= j complete (<=2 newer pending)
        __syncthreads();       // all threads' stages for buffer j visible

        const float* tb = tbase0 + (j & (NBUF - 1)) * BSTR;
        ABCp c = plane_abc(tb, ty, x0, hasM, hasP, TWO2);
        if (j >= 2)
            acc += emit4(m2, m1, c, TWO2, EPS2);
        m2 = m1; m1 = c;

        __syncthreads();       // reads of buffer (j-1)&3 done before overwrite
        if (j + 3 < NP)
            load_plane(sbuf, (j + 3) & (NBUF - 1), pred, targ, batchOff,
                       zstart - 1 + j + 3, ybase, tid);
        CP_COMMIT();           // every thread commits (group may be empty)
    }

    // ---------- block reduction (deterministic) ----------
    float v = acc;
    #pragma unroll
    for (int o = 16; o > 0; o >>= 1)
        v += __shfl_down_sync(FULL, v, o);
    if (lane == 0) wsum[wid] = v;
    __syncthreads();

    if (tid == 0) {
        float s = 0.f;
        #pragma unroll
        for (int w = 0; w < NTHREADS / 32; ++w) s += wsum[w];
        g_partial[blockIdx.z * GY + blockIdx.y] = s;
        __threadfence();
        unsigned d = atomicAdd(&g_done, 1u);
        lastFlag = (d == NBLK - 1);
    }
    __syncthreads();

    // ---------- last block folds all partials (fixed order -> deterministic) ----------
    if (lastFlag) {
        const volatile float* gp = g_partial;
        float s = 0.f;
        for (int i = tid; i < NBLK; i += NTHREADS)
            s += gp[i];
        #pragma unroll
        for (int o = 16; o > 0; o >>= 1)
            s += __shfl_down_sync(FULL, s, o);
        if (lane == 0) wsum[wid] = s;
        __syncthreads();
        if (tid == 0) {
            float tot = 0.f;
            #pragma unroll
            for (int w = 0; w < NTHREADS / 32; ++w) tot += wsum[w];
            out[0] = tot * (float)(0.5 / NVOX);   // 0.5: both lanes accumulated
            g_done = 0;    // reset for next graph replay
        }
    }
}

extern "C" void kernel_launch(void* const* d_in, const int* in_sizes, int n_in,
                              void* d_out, int out_size) {
    const float* pred = (const float*)d_in[0];
    const float* targ = (const float*)d_in[1];
    dim3 blk(BX, BY, 1);
    dim3 grd(1, GY, NCID);
    sobel_loss_fused<<<grd, blk>>>(pred, targ, (float*)d_out);
}